// round 4
// baseline (speedup 1.0000x reference)
#include <cuda_runtime.h>
#include <cstdint>

#define NUM_RELS 500
#define N_NODES  200000
#define ENT_DIM  128

// Per-relation scalars padded to 8 floats: [S_pp, S_pr, S_p, S_rr, S_r, 0,0,0]
__device__ float4 g_rel_c[NUM_RELS * 2];
// Per-node scalars: x = emb_p . emb,  y = sum(emb)
__device__ float2 g_node_h[N_NODES];
__device__ float2 g_node_t[N_NODES];

__device__ __forceinline__ float warp_sum(float v) {
    #pragma unroll
    for (int o = 16; o > 0; o >>= 1)
        v += __shfl_xor_sync(0xFFFFFFFFu, v, o);
    return v;
}

// Fused precompute. Each warp handles TWO nodes (8 outstanding float4 loads
// per lane) to maximize memory-level parallelism; relation warps at the tail.
//   warp <  ceil(N_NODES/2)          : nodes {2w, 2w+1}, all 4 entity tables
//   next NUM_RELS warps              : per-relation scalars
__global__ __launch_bounds__(256)
void precompute_kernel(const float* __restrict__ head_emb,
                       const float* __restrict__ head_emb_p,
                       const float* __restrict__ tail_emb,
                       const float* __restrict__ tail_emb_p,
                       const float* __restrict__ rel_emb,
                       const float* __restrict__ rel_emb_p) {
    const int NODE_WARPS = (N_NODES + 1) / 2;
    int warp = (blockIdx.x * blockDim.x + threadIdx.x) >> 5;
    int lane = threadIdx.x & 31;

    if (warp < NODE_WARPS) {
        int n0 = warp * 2;
        int n1 = n0 + 1;
        bool has1 = (n1 < N_NODES);

        const float4* h4a  = reinterpret_cast<const float4*>(head_emb   + (size_t)n0 * ENT_DIM);
        const float4* hp4a = reinterpret_cast<const float4*>(head_emb_p + (size_t)n0 * ENT_DIM);
        const float4* t4a  = reinterpret_cast<const float4*>(tail_emb   + (size_t)n0 * ENT_DIM);
        const float4* tp4a = reinterpret_cast<const float4*>(tail_emb_p + (size_t)n0 * ENT_DIM);
        int n1c = has1 ? n1 : n0;
        const float4* h4b  = reinterpret_cast<const float4*>(head_emb   + (size_t)n1c * ENT_DIM);
        const float4* hp4b = reinterpret_cast<const float4*>(head_emb_p + (size_t)n1c * ENT_DIM);
        const float4* t4b  = reinterpret_cast<const float4*>(tail_emb   + (size_t)n1c * ENT_DIM);
        const float4* tp4b = reinterpret_cast<const float4*>(tail_emb_p + (size_t)n1c * ENT_DIM);

        // Issue all 8 loads up front (independent).
        float4 ha  = h4a[lane];
        float4 hpa = hp4a[lane];
        float4 ta  = t4a[lane];
        float4 tpa = tp4a[lane];
        float4 hb  = h4b[lane];
        float4 hpb = hp4b[lane];
        float4 tb  = t4b[lane];
        float4 tpb = tp4b[lane];

        float ah0 = hpa.x*ha.x + hpa.y*ha.y + hpa.z*ha.z + hpa.w*ha.w;
        float bh0 = ha.x + ha.y + ha.z + ha.w;
        float at0 = tpa.x*ta.x + tpa.y*ta.y + tpa.z*ta.z + tpa.w*ta.w;
        float bt0 = ta.x + ta.y + ta.z + ta.w;
        float ah1 = hpb.x*hb.x + hpb.y*hb.y + hpb.z*hb.z + hpb.w*hb.w;
        float bh1 = hb.x + hb.y + hb.z + hb.w;
        float at1 = tpb.x*tb.x + tpb.y*tb.y + tpb.z*tb.z + tpb.w*tb.w;
        float bt1 = tb.x + tb.y + tb.z + tb.w;

        ah0 = warp_sum(ah0);
        bh0 = warp_sum(bh0);
        at0 = warp_sum(at0);
        bt0 = warp_sum(bt0);
        ah1 = warp_sum(ah1);
        bh1 = warp_sum(bh1);
        at1 = warp_sum(at1);
        bt1 = warp_sum(bt1);

        if (lane == 0) {
            g_node_h[n0] = make_float2(ah0, bh0);
            g_node_t[n0] = make_float2(at0, bt0);
            if (has1) {
                g_node_h[n1] = make_float2(ah1, bh1);
                g_node_t[n1] = make_float2(at1, bt1);
            }
        }
    } else if (warp < NODE_WARPS + NUM_RELS) {
        int rel = warp - NODE_WARPS;
        const float4* r4 = reinterpret_cast<const float4*>(rel_emb   + (size_t)rel * ENT_DIM);
        const float4* p4 = reinterpret_cast<const float4*>(rel_emb_p + (size_t)rel * ENT_DIM);
        float4 q = r4[lane];
        float4 p = p4[lane];

        float s_pp = p.x*p.x + p.y*p.y + p.z*p.z + p.w*p.w;
        float s_pr = p.x*q.x + p.y*q.y + p.z*q.z + p.w*q.w;
        float s_p  = p.x + p.y + p.z + p.w;
        float s_rr = q.x*q.x + q.y*q.y + q.z*q.z + q.w*q.w;
        float s_r  = q.x + q.y + q.z + q.w;

        s_pp = warp_sum(s_pp);
        s_pr = warp_sum(s_pr);
        s_p  = warp_sum(s_p);
        s_rr = warp_sum(s_rr);
        s_r  = warp_sum(s_r);

        if (lane == 0) {
            g_rel_c[rel * 2 + 0] = make_float4(s_pp, s_pr, s_p, s_rr);
            g_rel_c[rel * 2 + 1] = make_float4(s_r, 0.0f, 0.0f, 0.0f);
        }
    }
}

__device__ __forceinline__ float score_one(int hi, int ti, int ri) {
    float2 hc = g_node_h[hi];
    float2 tc = g_node_t[ti];
    float4 c0 = g_rel_c[ri * 2 + 0];
    float4 c1 = g_rel_c[ri * 2 + 1];
    float a = hc.x - tc.x;
    float b = hc.y - tc.y;
    return a*a*c0.x + 2.0f*a*c0.y + 2.0f*a*b*c0.z
         + c0.w + 2.0f*b*c1.x + (float)ENT_DIM * b*b;
}

// 4 rows per thread: int4 index loads, 8 independent node gathers in flight,
// float4 result store.
__global__ __launch_bounds__(256)
void transd_score_kernel(const int* __restrict__ head_idx,
                         const int* __restrict__ tail_idx,
                         const int* __restrict__ rel_idx,
                         float* __restrict__ out,
                         int B) {
    int t = blockIdx.x * blockDim.x + threadIdx.x;
    int base = t * 4;
    if (base + 3 < B) {
        int4 hi4 = *reinterpret_cast<const int4*>(head_idx + base);
        int4 ti4 = *reinterpret_cast<const int4*>(tail_idx + base);
        int4 ri4 = *reinterpret_cast<const int4*>(rel_idx  + base);

        // Issue all 8 node-scalar gathers before any dependent math.
        float2 h0 = g_node_h[hi4.x];
        float2 h1 = g_node_h[hi4.y];
        float2 h2 = g_node_h[hi4.z];
        float2 h3 = g_node_h[hi4.w];
        float2 t0 = g_node_t[ti4.x];
        float2 t1 = g_node_t[ti4.y];
        float2 t2 = g_node_t[ti4.z];
        float2 t3 = g_node_t[ti4.w];

        float4 c00 = g_rel_c[ri4.x * 2 + 0];
        float4 c01 = g_rel_c[ri4.x * 2 + 1];
        float4 c10 = g_rel_c[ri4.y * 2 + 0];
        float4 c11 = g_rel_c[ri4.y * 2 + 1];
        float4 c20 = g_rel_c[ri4.z * 2 + 0];
        float4 c21 = g_rel_c[ri4.z * 2 + 1];
        float4 c30 = g_rel_c[ri4.w * 2 + 0];
        float4 c31 = g_rel_c[ri4.w * 2 + 1];

        float4 res;
        {
            float a = h0.x - t0.x, b = h0.y - t0.y;
            res.x = a*a*c00.x + 2.0f*a*c00.y + 2.0f*a*b*c00.z
                  + c00.w + 2.0f*b*c01.x + (float)ENT_DIM * b*b;
        }
        {
            float a = h1.x - t1.x, b = h1.y - t1.y;
            res.y = a*a*c10.x + 2.0f*a*c10.y + 2.0f*a*b*c10.z
                  + c10.w + 2.0f*b*c11.x + (float)ENT_DIM * b*b;
        }
        {
            float a = h2.x - t2.x, b = h2.y - t2.y;
            res.z = a*a*c20.x + 2.0f*a*c20.y + 2.0f*a*b*c20.z
                  + c20.w + 2.0f*b*c21.x + (float)ENT_DIM * b*b;
        }
        {
            float a = h3.x - t3.x, b = h3.y - t3.y;
            res.w = a*a*c30.x + 2.0f*a*c30.y + 2.0f*a*b*c30.z
                  + c30.w + 2.0f*b*c31.x + (float)ENT_DIM * b*b;
        }
        *reinterpret_cast<float4*>(out + base) = res;
    } else {
        // Scalar tail.
        for (int i = base; i < B; i++)
            out[i] = score_one(head_idx[i], tail_idx[i], rel_idx[i]);
    }
}

extern "C" void kernel_launch(void* const* d_in, const int* in_sizes, int n_in,
                              void* d_out, int out_size) {
    const float* head_emb   = (const float*)d_in[0];
    const float* head_emb_p = (const float*)d_in[1];
    const float* tail_emb   = (const float*)d_in[2];
    const float* tail_emb_p = (const float*)d_in[3];
    const float* rel_emb    = (const float*)d_in[4];
    const float* rel_emb_p  = (const float*)d_in[5];
    const int*   head_idx   = (const int*)d_in[6];
    const int*   tail_idx   = (const int*)d_in[7];
    const int*   rel_idx    = (const int*)d_in[8];
    float* out = (float*)d_out;

    int B = in_sizes[6];

    // Fused per-node + per-relation precompute (streams all tables once).
    {
        int threads = 256;                 // 8 warps/block
        long long warps = (long long)((N_NODES + 1) / 2) + NUM_RELS;
        int blocks = (int)((warps * 32 + threads - 1) / threads);
        precompute_kernel<<<blocks, threads>>>(head_emb, head_emb_p,
                                               tail_emb, tail_emb_p,
                                               rel_emb, rel_emb_p);
    }

    // Closed-form score, 4 rows per thread.
    {
        int threads = 256;
        int rows_per_block = threads * 4;
        int blocks = (B + rows_per_block - 1) / rows_per_block;
        transd_score_kernel<<<blocks, threads>>>(head_idx, tail_idx, rel_idx,
                                                 out, B);
    }
}

// round 5
// speedup vs baseline: 1.0639x; 1.0639x over previous
#include <cuda_runtime.h>
#include <cstdint>

#define NUM_RELS 500
#define N_NODES  200000
#define ENT_DIM  128

// Per-relation scalars, SoA in gmem: [5][NUM_RELS] = S_pp, S_pr, S_p, S_rr, S_r
__device__ float g_rel_c[5][NUM_RELS];
// Per-node scalars: x = emb_p . emb,  y = sum(emb)
__device__ float2 g_node_h[N_NODES];
__device__ float2 g_node_t[N_NODES];

__device__ __forceinline__ float warp_sum(float v) {
    #pragma unroll
    for (int o = 16; o > 0; o >>= 1)
        v += __shfl_xor_sync(0xFFFFFFFFu, v, o);
    return v;
}

// Fused precompute (1 node per warp — best measured config):
//   warp <  N_NODES           : per-node scalars for all 4 entity tables
//   warp in [N_NODES, +RELS)  : per-relation scalars
__global__ __launch_bounds__(256)
void precompute_kernel(const float* __restrict__ head_emb,
                       const float* __restrict__ head_emb_p,
                       const float* __restrict__ tail_emb,
                       const float* __restrict__ tail_emb_p,
                       const float* __restrict__ rel_emb,
                       const float* __restrict__ rel_emb_p) {
    int warp = (blockIdx.x * blockDim.x + threadIdx.x) >> 5;
    int lane = threadIdx.x & 31;

    if (warp < N_NODES) {
        int node = warp;
        const float4* h4  = reinterpret_cast<const float4*>(head_emb   + (size_t)node * ENT_DIM);
        const float4* hp4 = reinterpret_cast<const float4*>(head_emb_p + (size_t)node * ENT_DIM);
        const float4* t4  = reinterpret_cast<const float4*>(tail_emb   + (size_t)node * ENT_DIM);
        const float4* tp4 = reinterpret_cast<const float4*>(tail_emb_p + (size_t)node * ENT_DIM);

        // Streaming loads: read-once data, evict-first.
        float4 h  = __ldcs(h4  + lane);
        float4 hp = __ldcs(hp4 + lane);
        float4 t  = __ldcs(t4  + lane);
        float4 tp = __ldcs(tp4 + lane);

        float ah = hp.x*h.x + hp.y*h.y + hp.z*h.z + hp.w*h.w;
        float bh = h.x + h.y + h.z + h.w;
        float at = tp.x*t.x + tp.y*t.y + tp.z*t.z + tp.w*t.w;
        float bt = t.x + t.y + t.z + t.w;

        ah = warp_sum(ah);
        bh = warp_sum(bh);
        at = warp_sum(at);
        bt = warp_sum(bt);

        if (lane == 0) {
            g_node_h[node] = make_float2(ah, bh);
            g_node_t[node] = make_float2(at, bt);
        }
    } else if (warp < N_NODES + NUM_RELS) {
        int rel = warp - N_NODES;
        const float4* r4 = reinterpret_cast<const float4*>(rel_emb   + (size_t)rel * ENT_DIM);
        const float4* p4 = reinterpret_cast<const float4*>(rel_emb_p + (size_t)rel * ENT_DIM);
        float4 q = __ldcs(r4 + lane);
        float4 p = __ldcs(p4 + lane);

        float s_pp = p.x*p.x + p.y*p.y + p.z*p.z + p.w*p.w;
        float s_pr = p.x*q.x + p.y*q.y + p.z*q.z + p.w*q.w;
        float s_p  = p.x + p.y + p.z + p.w;
        float s_rr = q.x*q.x + q.y*q.y + q.z*q.z + q.w*q.w;
        float s_r  = q.x + q.y + q.z + q.w;

        s_pp = warp_sum(s_pp);
        s_pr = warp_sum(s_pr);
        s_p  = warp_sum(s_p);
        s_rr = warp_sum(s_rr);
        s_r  = warp_sum(s_r);

        if (lane == 0) {
            g_rel_c[0][rel] = s_pp;
            g_rel_c[1][rel] = s_pr;
            g_rel_c[2][rel] = s_p;
            g_rel_c[3][rel] = s_rr;
            g_rel_c[4][rel] = s_r;
        }
    }
}

// Score: 2 rows per thread. Relation constants staged in SMEM (SoA) so the
// only L1tex random gathers are the node-scalar float2 loads.
__global__ __launch_bounds__(256)
void transd_score_kernel(const int* __restrict__ head_idx,
                         const int* __restrict__ tail_idx,
                         const int* __restrict__ rel_idx,
                         float* __restrict__ out,
                         int B) {
    __shared__ float s_pp[NUM_RELS];
    __shared__ float s_pr[NUM_RELS];
    __shared__ float s_p [NUM_RELS];
    __shared__ float s_rr[NUM_RELS];
    __shared__ float s_r [NUM_RELS];

    // Coalesced smem fill (2500 floats, ~10 iters at 256 threads).
    for (int i = threadIdx.x; i < NUM_RELS; i += blockDim.x) {
        s_pp[i] = g_rel_c[0][i];
        s_pr[i] = g_rel_c[1][i];
        s_p [i] = g_rel_c[2][i];
        s_rr[i] = g_rel_c[3][i];
        s_r [i] = g_rel_c[4][i];
    }
    __syncthreads();

    int t = blockIdx.x * blockDim.x + threadIdx.x;
    int base = t * 2;
    if (base + 1 < B) {
        int2 hi2 = *reinterpret_cast<const int2*>(head_idx + base);
        int2 ti2 = *reinterpret_cast<const int2*>(tail_idx + base);
        int2 ri2 = *reinterpret_cast<const int2*>(rel_idx  + base);

        // All 4 node gathers in flight before dependent math.
        float2 h0 = __ldg(&g_node_h[hi2.x]);
        float2 h1 = __ldg(&g_node_h[hi2.y]);
        float2 t0 = __ldg(&g_node_t[ti2.x]);
        float2 t1 = __ldg(&g_node_t[ti2.y]);

        float2 res;
        {
            float a = h0.x - t0.x, b = h0.y - t0.y;
            int r = ri2.x;
            res.x = a*a*s_pp[r] + 2.0f*a*s_pr[r] + 2.0f*a*b*s_p[r]
                  + s_rr[r] + 2.0f*b*s_r[r] + (float)ENT_DIM * b*b;
        }
        {
            float a = h1.x - t1.x, b = h1.y - t1.y;
            int r = ri2.y;
            res.y = a*a*s_pp[r] + 2.0f*a*s_pr[r] + 2.0f*a*b*s_p[r]
                  + s_rr[r] + 2.0f*b*s_r[r] + (float)ENT_DIM * b*b;
        }
        *reinterpret_cast<float2*>(out + base) = res;
    } else {
        for (int i = base; i < B; i++) {
            float2 hc = g_node_h[head_idx[i]];
            float2 tc = g_node_t[tail_idx[i]];
            int r = rel_idx[i];
            float a = hc.x - tc.x, b = hc.y - tc.y;
            out[i] = a*a*s_pp[r] + 2.0f*a*s_pr[r] + 2.0f*a*b*s_p[r]
                   + s_rr[r] + 2.0f*b*s_r[r] + (float)ENT_DIM * b*b;
        }
    }
}

extern "C" void kernel_launch(void* const* d_in, const int* in_sizes, int n_in,
                              void* d_out, int out_size) {
    const float* head_emb   = (const float*)d_in[0];
    const float* head_emb_p = (const float*)d_in[1];
    const float* tail_emb   = (const float*)d_in[2];
    const float* tail_emb_p = (const float*)d_in[3];
    const float* rel_emb    = (const float*)d_in[4];
    const float* rel_emb_p  = (const float*)d_in[5];
    const int*   head_idx   = (const int*)d_in[6];
    const int*   tail_idx   = (const int*)d_in[7];
    const int*   rel_idx    = (const int*)d_in[8];
    float* out = (float*)d_out;

    int B = in_sizes[6];

    // Fused per-node + per-relation precompute (streams all tables once).
    {
        int threads = 256;                 // 8 warps/block
        long long warps = (long long)N_NODES + NUM_RELS;
        int blocks = (int)((warps * 32 + threads - 1) / threads);
        precompute_kernel<<<blocks, threads>>>(head_emb, head_emb_p,
                                               tail_emb, tail_emb_p,
                                               rel_emb, rel_emb_p);
    }

    // Closed-form score, 2 rows per thread, smem-resident rel constants.
    {
        int threads = 256;
        int rows_per_block = threads * 2;
        int blocks = (B + rows_per_block - 1) / rows_per_block;
        transd_score_kernel<<<blocks, threads>>>(head_idx, tail_idx, rel_idx,
                                                 out, B);
    }
}